// round 6
// baseline (speedup 1.0000x reference)
#include <cuda_runtime.h>
#include <cuda_bf16.h>
#include <cstdint>

// Problem shape (fixed by the dataset)
#define B_DIM 256
#define N_DIM 2048
#define K_DIM 2048
#define T_DIM 128

// LIF constants (alpha = exp(-0.1) rounded to f32)
#define ALPHA_F 0.9048374180359595731f
#define THRESH_F 1.0f

#define SPLITK 16
#define KS (K_DIM / SPLITK)   // 128  -> short per-CTA latency (~8us)
#define NCHUNK 4              // n-dimension pipeline chunks

// Accumulated I = x @ W (2 MB, L2-resident) + 3-plane exact bf16 split of x
__device__ float g_I[B_DIM * N_DIM];
__device__ __nv_bfloat16 g_xbf[3][B_DIM][K_DIM];

// ---------------------------------------------------------------------------
// Kernel Z: zero g_I (atomicAdd accumulation needs a clean buffer every call)
// ---------------------------------------------------------------------------
__global__ void __launch_bounds__(256) zero_kernel()
{
    const int i = blockIdx.x * blockDim.x + threadIdx.x;
    reinterpret_cast<float4*>(g_I)[i] = make_float4(0.f, 0.f, 0.f, 0.f);
}

// ---------------------------------------------------------------------------
// Kernel 0: exact 3-way bf16 split of x.  b0+b1+b2 == x bit-exactly.
// 2 independent float4 groups per thread (MLP) — was latency-bound.
// ---------------------------------------------------------------------------
__global__ void __launch_bounds__(256) split_kernel(const float* __restrict__ x)
{
    const int i0 = blockIdx.x * blockDim.x + threadIdx.x;   // 0..65535
#pragma unroll
    for (int r = 0; r < 2; r++) {
        const int i = i0 + r * 65536;
        const float4 v = reinterpret_cast<const float4*>(x)[i];
        const float e[4] = {v.x, v.y, v.z, v.w};
        unsigned short q0[4], q1[4], q2[4];
#pragma unroll
        for (int j = 0; j < 4; j++) {
            const float f = e[j];
            const __nv_bfloat16 h0 = __float2bfloat16_rn(f);
            const float r1 = __fadd_rn(f, -__bfloat162float(h0));
            const __nv_bfloat16 h1 = __float2bfloat16_rn(r1);
            const float r2 = __fadd_rn(r1, -__bfloat162float(h1));
            const __nv_bfloat16 h2 = __float2bfloat16_rn(r2);
            q0[j] = __bfloat16_as_ushort(h0);
            q1[j] = __bfloat16_as_ushort(h1);
            q2[j] = __bfloat16_as_ushort(h2);
        }
        uint2 u0, u1, u2;
        u0.x = (uint32_t)q0[0] | ((uint32_t)q0[1] << 16);
        u0.y = (uint32_t)q0[2] | ((uint32_t)q0[3] << 16);
        u1.x = (uint32_t)q1[0] | ((uint32_t)q1[1] << 16);
        u1.y = (uint32_t)q1[2] | ((uint32_t)q1[3] << 16);
        u2.x = (uint32_t)q2[0] | ((uint32_t)q2[1] << 16);
        u2.y = (uint32_t)q2[2] | ((uint32_t)q2[3] << 16);
        reinterpret_cast<uint2*>(&g_xbf[0][0][0])[i] = u0;
        reinterpret_cast<uint2*>(&g_xbf[1][0][0])[i] = u1;
        reinterpret_cast<uint2*>(&g_xbf[2][0][0])[i] = u2;
    }
}

// ---------------------------------------------------------------------------
// Kernel 1: tensor-core GEMM via mma.sync.m16n8k16 bf16 (layout proven in R5).
// CTA tile 64x128, BK=16, per-CTA K-depth KS=128 (SPLITK=16 z-CTAs).
// Epilogue: predicated atomicAdd into g_I (exact: partials are {x, 0...}).
// Launched per n-chunk: grid (4, 4, 16) = 256 CTAs, xchunk selects columns.
// ---------------------------------------------------------------------------
#define BM 64
#define BN 128
#define BK 16
#define AK 24
#define BW 136

#define LDSM_X4(d, addr) \
    asm volatile("ldmatrix.sync.aligned.m8n8.x4.shared.b16 {%0,%1,%2,%3}, [%4];" \
        : "=r"((d)[0]), "=r"((d)[1]), "=r"((d)[2]), "=r"((d)[3]) : "r"(addr))
#define LDSM_X4_T(d, addr) \
    asm volatile("ldmatrix.sync.aligned.m8n8.x4.trans.shared.b16 {%0,%1,%2,%3}, [%4];" \
        : "=r"((d)[0]), "=r"((d)[1]), "=r"((d)[2]), "=r"((d)[3]) : "r"(addr))
#define MMA_BF16(c, a, b0, b1) \
    asm volatile("mma.sync.aligned.m16n8k16.row.col.f32.bf16.bf16.f32 " \
        "{%0,%1,%2,%3}, {%4,%5,%6,%7}, {%8,%9}, {%0,%1,%2,%3};" \
        : "+f"((c)[0]), "+f"((c)[1]), "+f"((c)[2]), "+f"((c)[3]) \
        : "r"((a)[0]), "r"((a)[1]), "r"((a)[2]), "r"((a)[3]), "r"(b0), "r"(b1))

__global__ void __launch_bounds__(256, 2) gemm_kernel(const float* __restrict__ W,
                                                      int xchunk)
{
    __shared__ __nv_bfloat16 As[2][3][BM][AK];
    __shared__ __nv_bfloat16 Bs[2][BK][BW];

    const int tid  = threadIdx.x;
    const int lane = tid & 31;
    const int wid  = tid >> 5;
    const int col0 = (xchunk * 4 + blockIdx.x) * BN;
    const int row0 = blockIdx.y * BM;
    const int kz   = blockIdx.z;

    const int am = tid >> 2;
    const int ak = (tid & 3) * 4;
    const int bk = tid >> 4;
    const int bn = (tid & 15) * 8;

    const size_t PS = (size_t)B_DIM * K_DIM;
    const __nv_bfloat16* Ap = &g_xbf[0][0][0] +
        (size_t)(row0 + am) * K_DIM + kz * KS + ak;
    const float* Wp = W + (size_t)(kz * KS + bk) * N_DIM + col0 + bn;

    const int wm0 = (wid >> 2) * 32;
    const int wn0 = (wid & 3) * 32;
    const int lrow = ((lane >> 3) & 1) * 8 + (lane & 7);
    const int lcol = (lane >> 4) * 8;

    uint32_t as_base = (uint32_t)__cvta_generic_to_shared(&As[0][0][0][0]);
    uint32_t bs_base = (uint32_t)__cvta_generic_to_shared(&Bs[0][0][0]);

    float c[2][4][4];
#pragma unroll
    for (int mf = 0; mf < 2; mf++)
#pragma unroll
        for (int nf = 0; nf < 4; nf++)
#pragma unroll
            for (int r = 0; r < 4; r++) c[mf][nf][r] = 0.0f;

    uint2 areg[3];
    float4 w0, w1;

    auto gload = [&](int kt) {
#pragma unroll
        for (int p = 0; p < 3; p++)
            areg[p] = *reinterpret_cast<const uint2*>(Ap + p * PS + kt * BK);
        w0 = *reinterpret_cast<const float4*>(Wp + (size_t)kt * BK * N_DIM);
        w1 = *reinterpret_cast<const float4*>(Wp + (size_t)kt * BK * N_DIM + 4);
    };
    auto sstore = [&](int nb) {
#pragma unroll
        for (int p = 0; p < 3; p++)
            *reinterpret_cast<uint2*>(&As[nb][p][am][ak]) = areg[p];
        __nv_bfloat162 t0 = __floats2bfloat162_rn(w0.x, w0.y);
        __nv_bfloat162 t1 = __floats2bfloat162_rn(w0.z, w0.w);
        __nv_bfloat162 t2 = __floats2bfloat162_rn(w1.x, w1.y);
        __nv_bfloat162 t3 = __floats2bfloat162_rn(w1.z, w1.w);
        uint4 u;
        u.x = *reinterpret_cast<uint32_t*>(&t0);
        u.y = *reinterpret_cast<uint32_t*>(&t1);
        u.z = *reinterpret_cast<uint32_t*>(&t2);
        u.w = *reinterpret_cast<uint32_t*>(&t3);
        *reinterpret_cast<uint4*>(&Bs[nb][bk][bn]) = u;
    };

    gload(0);
    sstore(0);
    __syncthreads();

    const int NT = KS / BK;   // 8
    int buf = 0;
    for (int kt = 0; kt < NT; kt++) {
        if (kt + 1 < NT) gload(kt + 1);

        uint32_t a[3][2][4];
        uint32_t b[2][4];
#pragma unroll
        for (int p = 0; p < 3; p++)
#pragma unroll
            for (int mf = 0; mf < 2; mf++) {
                uint32_t addr = as_base + 2u * (uint32_t)(
                    (((buf * 3 + p) * BM) + wm0 + mf * 16 + lrow) * AK + lcol);
                LDSM_X4(a[p][mf], addr);
            }
#pragma unroll
        for (int np = 0; np < 2; np++) {
            uint32_t addr = bs_base + 2u * (uint32_t)(
                (buf * BK + lrow) * BW + wn0 + np * 16 + lcol);
            LDSM_X4_T(b[np], addr);
        }

#pragma unroll
        for (int mf = 0; mf < 2; mf++)
#pragma unroll
            for (int nf = 0; nf < 4; nf++) {
                const uint32_t b0 = b[nf >> 1][(nf & 1) * 2];
                const uint32_t b1 = b[nf >> 1][(nf & 1) * 2 + 1];
                MMA_BF16(c[mf][nf], a[0][mf], b0, b1);
                MMA_BF16(c[mf][nf], a[1][mf], b0, b1);
                MMA_BF16(c[mf][nf], a[2][mf], b0, b1);
            }

        if (kt + 1 < NT) sstore(buf ^ 1);
        __syncthreads();
        buf ^= 1;
    }

    // Epilogue: accumulate into g_I; skip exact zeros (most of the 16 partials)
    const int gq = lane >> 2;
    const int t4 = lane & 3;
#pragma unroll
    for (int mf = 0; mf < 2; mf++)
#pragma unroll
        for (int nf = 0; nf < 4; nf++) {
            const int r  = row0 + wm0 + mf * 16 + gq;
            const int cc = col0 + wn0 + nf * 8 + t4 * 2;
            float* p = g_I + (size_t)r * N_DIM + cc;
            if (c[mf][nf][0] != 0.0f) atomicAdd(p,     c[mf][nf][0]);
            if (c[mf][nf][1] != 0.0f) atomicAdd(p + 1, c[mf][nf][1]);
            float* q = g_I + (size_t)(r + 8) * N_DIM + cc;
            if (c[mf][nf][2] != 0.0f) atomicAdd(q,     c[mf][nf][2]);
            if (c[mf][nf][3] != 0.0f) atomicAdd(q + 1, c[mf][nf][3]);
        }
}

// ---------------------------------------------------------------------------
// Kernel 2: LIF recurrence for one n-chunk of 512 columns.
//   u = rn(rn(ALPHA*V) + I); V' = Z ? 0 : u; Z' = (V' >= 1)
// ---------------------------------------------------------------------------
__global__ void __launch_bounds__(256) spike_kernel(float* __restrict__ out,
                                                    int n_off)
{
    const int g    = blockIdx.x * blockDim.x + threadIdx.x;  // 0..32767
    const int b    = g >> 7;             // 0..255
    const int nloc = g & 127;            // 0..127 float4 groups in chunk
    const int n    = n_off + nloc * 4;

    const float4 I4 = *reinterpret_cast<const float4*>(g_I + (size_t)b * N_DIM + n);

    float v0 = 0.f, v1 = 0.f, v2 = 0.f, v3 = 0.f;
    bool  s0 = false, s1 = false, s2 = false, s3 = false;

    float* outp = out + (size_t)b * T_DIM * N_DIM + n;

#pragma unroll 8
    for (int t = 0; t < T_DIM; t++) {
        float u0 = __fadd_rn(__fmul_rn(ALPHA_F, v0), I4.x);
        float u1 = __fadd_rn(__fmul_rn(ALPHA_F, v1), I4.y);
        float u2 = __fadd_rn(__fmul_rn(ALPHA_F, v2), I4.z);
        float u3 = __fadd_rn(__fmul_rn(ALPHA_F, v3), I4.w);
        v0 = s0 ? 0.0f : u0;
        v1 = s1 ? 0.0f : u1;
        v2 = s2 ? 0.0f : u2;
        v3 = s3 ? 0.0f : u3;
        s0 = (v0 >= THRESH_F);
        s1 = (v1 >= THRESH_F);
        s2 = (v2 >= THRESH_F);
        s3 = (v3 >= THRESH_F);
        float4 z = make_float4(s0 ? 1.0f : 0.0f, s1 ? 1.0f : 0.0f,
                               s2 ? 1.0f : 0.0f, s3 ? 1.0f : 0.0f);
        __stcs(reinterpret_cast<float4*>(outp), z);
        outp += N_DIM;
    }
}

// ---------------------------------------------------------------------------
// Chunked pipeline: GEMM chunks on the default stream; spike chunks on s2
// gated by events -> spike store stream hides GEMM chunks 1..3.
// Streams/events created once on the first (uncaptured) call; the enqueued
// work is identical on every call.
// ---------------------------------------------------------------------------
extern "C" void kernel_launch(void* const* d_in, const int* in_sizes, int n_in,
                              void* d_out, int out_size)
{
    const float* x = (const float*)d_in[0];   // [256, 2048]
    const float* W = (const float*)d_in[1];   // [2048, 2048]
    float* out = (float*)d_out;               // [256, 128, 2048]

    static cudaStream_t s2 = nullptr;
    static cudaEvent_t eg[NCHUNK];
    static cudaEvent_t es = nullptr;
    if (s2 == nullptr) {
        cudaStreamCreate(&s2);
        for (int i = 0; i < NCHUNK; i++)
            cudaEventCreateWithFlags(&eg[i], cudaEventDisableTiming);
        cudaEventCreateWithFlags(&es, cudaEventDisableTiming);
    }

    zero_kernel<<<(B_DIM * N_DIM / 4) / 256, 256>>>();
    split_kernel<<<256, 256>>>(x);

    for (int i = 0; i < NCHUNK; i++) {
        dim3 gg(4, B_DIM / BM, SPLITK);   // (4, 4, 16) = 256 CTAs
        gemm_kernel<<<gg, 256>>>(W, i);
        cudaEventRecord(eg[i], 0);
        cudaStreamWaitEvent(s2, eg[i], 0);
        spike_kernel<<<128, 256, 0, s2>>>(out, i * (N_DIM / NCHUNK));
    }

    cudaEventRecord(es, s2);
    cudaStreamWaitEvent(0, es, 0);
}